// round 5
// baseline (speedup 1.0000x reference)
#include <cuda_runtime.h>

// Problem constants
#define B_   8
#define T_   1024
#define E_   256
#define H_   8
#define HE_  2048   // H_*E_

// Projection/FC GEMM tile config (unchanged from round 4)
#define BM   128
#define BN   128
#define BK   16
#define BKP  20     // [m][k] smem row stride (words)
#define BNP  136    // [k][n] smem row stride (words)

#define NEG_INF __int_as_float(0xff800000)
#define POS_INF __int_as_float(0x7f800000)

// Scratch (static device arrays: allocation-guard-safe)
__device__ float g_qkv[3ULL * B_ * T_ * HE_];   // Q, K, V each [B, T, HE] (tf32-rounded)
__device__ float g_o[(size_t)B_ * T_ * HE_];    // attn@V [B, T, HE] (tf32-rounded)
__device__ float g_xr[(size_t)B_ * T_ * E_];    // tf32-rounded x
__device__ float g_wr[4ULL * E_ * HE_];         // tf32-rounded Wq, Wk, Wv, Wfc

__device__ __forceinline__ unsigned f2tf32(float f) {
    unsigned u;
    asm("cvt.rna.tf32.f32 %0, %1;" : "=r"(u) : "f"(f));
    return u;
}
__device__ __forceinline__ float rtf(float f) { return __uint_as_float(f2tf32(f)); }

__device__ __forceinline__ void mma_tf32(float c[4], const unsigned a[4], const unsigned b[2]) {
    asm("mma.sync.aligned.m16n8k8.row.col.f32.tf32.tf32.f32 "
        "{%0,%1,%2,%3}, {%4,%5,%6,%7}, {%8,%9}, {%0,%1,%2,%3};"
        : "+f"(c[0]), "+f"(c[1]), "+f"(c[2]), "+f"(c[3])
        : "r"(a[0]), "r"(a[1]), "r"(a[2]), "r"(a[3]), "r"(b[0]), "r"(b[1]));
}

__device__ __forceinline__ void cp16(void* smem_dst, const void* gmem_src) {
    unsigned d = (unsigned)__cvta_generic_to_shared(smem_dst);
    asm volatile("cp.async.cg.shared.global [%0], [%1], 16;" :: "r"(d), "l"(gmem_src));
}
#define CP_COMMIT()  asm volatile("cp.async.commit_group;")
#define CP_WAIT1()   asm volatile("cp.async.wait_group 1;")
#define CP_WAIT0()   asm volatile("cp.async.wait_group 0;")

// ===========================================================================
// Generic tensor-core GEMM mainloop (for qkv / fc) — unchanged from round 4
// ===========================================================================
template <bool BT>
__device__ __forceinline__ void gemm_tc(const float* __restrict__ A, int lda,
                                        const float* __restrict__ Bm, int ldb,
                                        int K, float acc[4][4][4])
{
    __shared__ float As[2][BM * BKP];
    __shared__ float Bs[2][BM * BKP];

    const int tid  = threadIdx.x;
    const int lane = tid & 31;
    const int warp = tid >> 5;
    const int wm   = warp >> 2;
    const int wn   = warp & 3;
    const int g    = lane >> 2;
    const int q    = lane & 3;

    auto stage = [&](int buf, int k0) {
        #pragma unroll
        for (int i = 0; i < 2; i++) {
            int c  = tid + i * 256;
            int m  = c >> 2;
            int ko = (c & 3) * 4;
            cp16(&As[buf][m * BKP + ko], A + (size_t)m * lda + k0 + ko);
        }
        #pragma unroll
        for (int i = 0; i < 2; i++) {
            int c = tid + i * 256;
            if (BT) {
                int n  = c >> 2;
                int ko = (c & 3) * 4;
                cp16(&Bs[buf][n * BKP + ko], Bm + (size_t)n * ldb + k0 + ko);
            } else {
                int kk = c >> 5;
                int no = (c & 31) * 4;
                cp16(&Bs[buf][kk * BNP + no], Bm + (size_t)(k0 + kk) * ldb + no);
            }
        }
        CP_COMMIT();
    };

    stage(0, 0);

    const int niter = K / BK;
    for (int it = 0; it < niter; it++) {
        const int buf = it & 1;
        if (it + 1 < niter) { stage(buf ^ 1, (it + 1) * BK); CP_WAIT1(); }
        else                { CP_WAIT0(); }
        __syncthreads();

        #pragma unroll
        for (int ks = 0; ks < 2; ks++) {
            const int kb = ks * 8;
            unsigned a[4][4], b[4][2];
            #pragma unroll
            for (int mi = 0; mi < 4; mi++) {
                int m = wm * 64 + mi * 16;
                a[mi][0] = __float_as_uint(As[buf][(m + g    ) * BKP + kb + q    ]);
                a[mi][1] = __float_as_uint(As[buf][(m + g + 8) * BKP + kb + q    ]);
                a[mi][2] = __float_as_uint(As[buf][(m + g    ) * BKP + kb + q + 4]);
                a[mi][3] = __float_as_uint(As[buf][(m + g + 8) * BKP + kb + q + 4]);
            }
            #pragma unroll
            for (int ni = 0; ni < 4; ni++) {
                int n = wn * 32 + ni * 8;
                if (BT) {
                    b[ni][0] = __float_as_uint(Bs[buf][(n + g) * BKP + kb + q    ]);
                    b[ni][1] = __float_as_uint(Bs[buf][(n + g) * BKP + kb + q + 4]);
                } else {
                    b[ni][0] = __float_as_uint(Bs[buf][(kb + q    ) * BNP + n + g]);
                    b[ni][1] = __float_as_uint(Bs[buf][(kb + q + 4) * BNP + n + g]);
                }
            }
            #pragma unroll
            for (int mi = 0; mi < 4; mi++)
                #pragma unroll
                for (int ni = 0; ni < 4; ni++)
                    mma_tf32(acc[mi][ni], a[mi], b[ni]);
        }
        __syncthreads();
    }
}

struct Frag {
    int wm, wn, g, q;
    __device__ __forceinline__ Frag() {
        int tid = threadIdx.x, lane = tid & 31, warp = tid >> 5;
        wm = warp >> 2; wn = warp & 3; g = lane >> 2; q = lane & 3;
    }
    __device__ __forceinline__ int row(int mi, int hi) const { return wm * 64 + mi * 16 + g + hi * 8; }
    __device__ __forceinline__ int col(int ni) const { return wn * 32 + ni * 8 + 2 * q; }
};

// ===========================================================================
// Stage 0: pre-round inputs to tf32
// ===========================================================================
#define XR_N   ((size_t)B_ * T_ * E_)
#define W_N    ((size_t)E_ * HE_)
__global__ __launch_bounds__(256) void round_kernel(const float* __restrict__ x,
                                                    const float* __restrict__ Wq,
                                                    const float* __restrict__ Wk,
                                                    const float* __restrict__ Wv,
                                                    const float* __restrict__ Wfc)
{
    size_t i = ((size_t)blockIdx.x * 256 + threadIdx.x) * 4;
    const float* src;
    float* dst;
    size_t off;
    if (i < XR_N)                 { src = x;   dst = g_xr;            off = i; }
    else if (i < XR_N + W_N)      { src = Wq;  dst = g_wr;            off = i - XR_N; }
    else if (i < XR_N + 2 * W_N)  { src = Wk;  dst = g_wr + W_N;      off = i - XR_N - W_N; }
    else if (i < XR_N + 3 * W_N)  { src = Wv;  dst = g_wr + 2 * W_N;  off = i - XR_N - 2 * W_N; }
    else                          { src = Wfc; dst = g_wr + 3 * W_N;  off = i - XR_N - 3 * W_N; }
    float4 v = *(const float4*)(src + off);
    v.x = rtf(v.x); v.y = rtf(v.y); v.z = rtf(v.z); v.w = rtf(v.w);
    *(float4*)(dst + off) = v;
}

// ===========================================================================
// Stage 1: QKV projections (Q scaled 1/16), outputs tf32-rounded
// ===========================================================================
__global__ __launch_bounds__(256) void qkv_kernel()
{
    const int z = blockIdx.z;
    const float* W = g_wr + (size_t)z * W_N;
    const float scale = (z == 0) ? 0.0625f : 1.0f;
    float* C = g_qkv + (size_t)z * B_ * T_ * HE_;

    const int m0 = blockIdx.y * BM;
    const int n0 = blockIdx.x * BN;

    float acc[4][4][4] = {};
    gemm_tc<false>(g_xr + (size_t)m0 * E_, E_, W + n0, HE_, E_, acc);

    Frag f;
    #pragma unroll
    for (int mi = 0; mi < 4; mi++)
        #pragma unroll
        for (int ni = 0; ni < 4; ni++) {
            int c = n0 + f.col(ni);
            *(float2*)&C[(size_t)(m0 + f.row(mi, 0)) * HE_ + c] =
                make_float2(rtf(acc[mi][ni][0] * scale), rtf(acc[mi][ni][1] * scale));
            *(float2*)&C[(size_t)(m0 + f.row(mi, 1)) * HE_ + c] =
                make_float2(rtf(acc[mi][ni][2] * scale), rtf(acc[mi][ni][3] * scale));
        }
}

// ===========================================================================
// Stage 2: FUSED flash attention: S = Q.K^T, mask, online softmax, P.V
// One CTA = one (b,h) x 64-query tile. 256 threads, 8 warps (2x4).
// Smem (floats): Qs 64x260 | Ks 2x128x20 | Vs 2x16x264 | Ps 64x132 | red 4x64
// ===========================================================================
#define QS_STRIDE 260
#define KS_STRIDE 20
#define VS_STRIDE 264
#define PS_STRIDE 132
#define QS_OFF   0
#define KS_OFF   (64 * QS_STRIDE)                 // 16640
#define VS_OFF   (KS_OFF + 2 * 128 * KS_STRIDE)   // 21760
#define PS_OFF   (VS_OFF + 2 * 16 * VS_STRIDE)    // 30208
#define RED_OFF  (PS_OFF + 64 * PS_STRIDE)        // 38656
#define FLASH_SMEM_WORDS (RED_OFF + 4 * 64)       // 38912
#define FLASH_SMEM_BYTES (FLASH_SMEM_WORDS * 4)   // 155648

__global__ __launch_bounds__(256, 1) void flash_kernel(const int* __restrict__ mask)
{
    extern __shared__ float sm[];
    float* Qs  = sm + QS_OFF;
    float* Ks  = sm + KS_OFF;
    float* Vs  = sm + VS_OFF;
    float* Ps  = sm + PS_OFF;
    float* red = sm + RED_OFF;

    const int tid  = threadIdx.x;
    const int lane = tid & 31;
    const int warp = tid >> 5;
    const int wm   = warp >> 2;    // 0..1
    const int wn   = warp & 3;     // 0..3
    const int g    = lane >> 2;    // 0..7
    const int q    = lane & 3;     // 0..3

    const int z = blockIdx.y;      // b*H + h
    const int b = z >> 3;
    const int h = z & 7;
    const int m0 = blockIdx.x * 64;

    const float* Qg = g_qkv + (size_t)b * T_ * HE_ + (size_t)m0 * HE_ + h * E_;
    const float* Kg = g_qkv + (size_t)B_ * T_ * HE_ + (size_t)b * T_ * HE_ + h * E_;
    const float* Vg = g_qkv + 2ULL * B_ * T_ * HE_ + (size_t)b * T_ * HE_ + h * E_;
    const int*   mrow = mask + (size_t)b * T_ * T_;

    auto stageK = [&](int buf, int kb, int c) {
        #pragma unroll
        for (int i = 0; i < 2; i++) {
            int idx = tid + i * 256;
            int n   = idx >> 2;
            int ko  = (idx & 3) * 4;
            cp16(&Ks[buf * (128 * KS_STRIDE) + n * KS_STRIDE + ko],
                 Kg + (size_t)(kb * 128 + n) * HE_ + c * 16 + ko);
        }
    };
    auto stageV = [&](int buf, int kb, int c) {
        #pragma unroll
        for (int i = 0; i < 4; i++) {
            int idx = tid + i * 256;
            int kk  = idx >> 6;
            int no  = (idx & 63) * 4;
            cp16(&Vs[buf * (16 * VS_STRIDE) + kk * VS_STRIDE + no],
                 Vg + (size_t)(kb * 128 + c * 16 + kk) * HE_ + no);
        }
    };

    // local rows owned by this thread: lr[mi][hi]
    int lr[2][2];
    #pragma unroll
    for (int mi = 0; mi < 2; mi++)
        #pragma unroll
        for (int hi = 0; hi < 2; hi++)
            lr[mi][hi] = wm * 32 + mi * 16 + g + 8 * hi;

    // running softmax state + output accumulator
    float m_r[2][2], l_r[2][2];
    float oacc[2][8][4] = {};
    #pragma unroll
    for (int mi = 0; mi < 2; mi++)
        #pragma unroll
        for (int hi = 0; hi < 2; hi++) { m_r[mi][hi] = NEG_INF; l_r[mi][hi] = 0.0f; }

    // prologue: Q tile (once) + first K chunk in one group
    #pragma unroll
    for (int i = 0; i < 16; i++) {
        int idx = tid + i * 256;
        int m   = idx >> 6;
        int ko  = (idx & 63) * 4;
        cp16(&Qs[m * QS_STRIDE + ko], Qg + (size_t)m * HE_ + ko);
    }
    stageK(0, 0, 0);
    CP_COMMIT();

    for (int kb = 0; kb < 8; kb++) {
        // ------------------ S phase: S = Q . K^T over K=256 ------------------
        float sacc[2][4][4] = {};
        for (int c = 0; c < 16; c++) {
            __syncthreads();                       // protect buf about to be staged
            if (c < 15) stageK((c + 1) & 1, kb, c + 1);
            else        stageV(0, kb, 0);          // prefetch first V chunk
            CP_COMMIT();
            CP_WAIT1();
            __syncthreads();

            const int buf = c & 1;
            #pragma unroll
            for (int ks = 0; ks < 2; ks++) {
                const int kq = c * 16 + ks * 8;
                unsigned a[2][4], bf[4][2];
                #pragma unroll
                for (int mi = 0; mi < 2; mi++) {
                    int m = wm * 32 + mi * 16;
                    a[mi][0] = __float_as_uint(Qs[(m + g    ) * QS_STRIDE + kq + q    ]);
                    a[mi][1] = __float_as_uint(Qs[(m + g + 8) * QS_STRIDE + kq + q    ]);
                    a[mi][2] = __float_as_uint(Qs[(m + g    ) * QS_STRIDE + kq + q + 4]);
                    a[mi][3] = __float_as_uint(Qs[(m + g + 8) * QS_STRIDE + kq + q + 4]);
                }
                #pragma unroll
                for (int ni = 0; ni < 4; ni++) {
                    int n = wn * 32 + ni * 8;
                    bf[ni][0] = __float_as_uint(Ks[buf * (128 * KS_STRIDE) + (n + g) * KS_STRIDE + ks * 8 + q    ]);
                    bf[ni][1] = __float_as_uint(Ks[buf * (128 * KS_STRIDE) + (n + g) * KS_STRIDE + ks * 8 + q + 4]);
                }
                #pragma unroll
                for (int mi = 0; mi < 2; mi++)
                    #pragma unroll
                    for (int ni = 0; ni < 4; ni++)
                        mma_tf32(sacc[mi][ni], a[mi], bf[ni]);
            }
        }

        // ------------------ mask + online softmax ------------------
        #pragma unroll
        for (int mi = 0; mi < 2; mi++)
            #pragma unroll
            for (int hi = 0; hi < 2; hi++) {
                size_t roff = (size_t)(m0 + lr[mi][hi]) * T_ + kb * 128;
                #pragma unroll
                for (int ni = 0; ni < 4; ni++) {
                    int2 mk = *(const int2*)&mrow[roff + wn * 32 + ni * 8 + 2 * q];
                    if (mk.x) sacc[mi][ni][2 * hi    ] = NEG_INF;
                    if (mk.y) sacc[mi][ni][2 * hi + 1] = NEG_INF;
                }
            }

        // block row max: quad shfl, then cross-warp via red[wn][row]
        float rmx[2][2];
        #pragma unroll
        for (int mi = 0; mi < 2; mi++)
            #pragma unroll
            for (int hi = 0; hi < 2; hi++) {
                float m_ = NEG_INF;
                #pragma unroll
                for (int ni = 0; ni < 4; ni++) {
                    m_ = fmaxf(m_, sacc[mi][ni][2 * hi]);
                    m_ = fmaxf(m_, sacc[mi][ni][2 * hi + 1]);
                }
                m_ = fmaxf(m_, __shfl_xor_sync(0xffffffff, m_, 1));
                m_ = fmaxf(m_, __shfl_xor_sync(0xffffffff, m_, 2));
                rmx[mi][hi] = m_;
            }
        if (q == 0) {
            #pragma unroll
            for (int mi = 0; mi < 2; mi++)
                #pragma unroll
                for (int hi = 0; hi < 2; hi++)
                    red[wn * 64 + lr[mi][hi]] = rmx[mi][hi];
        }
        __syncthreads();

        float mnew[2][2], scl[2][2];
        #pragma unroll
        for (int mi = 0; mi < 2; mi++)
            #pragma unroll
            for (int hi = 0; hi < 2; hi++) {
                int r = lr[mi][hi];
                float mb = fmaxf(fmaxf(red[r], red[64 + r]), fmaxf(red[128 + r], red[192 + r]));
                float mn = fmaxf(m_r[mi][hi], mb);
                // NaN-safe: -inf - -inf -> NaN -> fmaxf picks -88
                scl[mi][hi]  = __expf(fmaxf(m_r[mi][hi] - mn, -88.0f));
                mnew[mi][hi] = mn;
                m_r[mi][hi]  = mn;
            }
        __syncthreads();   // red reads done before reuse

        // p = exp(s - mnew), row sums
        float rs[2][2] = {};
        #pragma unroll
        for (int mi = 0; mi < 2; mi++)
            #pragma unroll
            for (int ni = 0; ni < 4; ni++)
                #pragma unroll
                for (int hi = 0; hi < 2; hi++)
                    #pragma unroll
                    for (int j = 0; j < 2; j++) {
                        float p = __expf(fmaxf(sacc[mi][ni][2 * hi + j] - mnew[mi][hi], -88.0f));
                        sacc[mi][ni][2 * hi + j] = p;
                        rs[mi][hi] += p;
                    }
        #pragma unroll
        for (int mi = 0; mi < 2; mi++)
            #pragma unroll
            for (int hi = 0; hi < 2; hi++) {
                float s = rs[mi][hi];
                s += __shfl_xor_sync(0xffffffff, s, 1);
                s += __shfl_xor_sync(0xffffffff, s, 2);
                rs[mi][hi] = s;
            }
        if (q == 0) {
            #pragma unroll
            for (int mi = 0; mi < 2; mi++)
                #pragma unroll
                for (int hi = 0; hi < 2; hi++)
                    red[wn * 64 + lr[mi][hi]] = rs[mi][hi];
        }
        __syncthreads();
        #pragma unroll
        for (int mi = 0; mi < 2; mi++)
            #pragma unroll
            for (int hi = 0; hi < 2; hi++) {
                int r = lr[mi][hi];
                float ladd = red[r] + red[64 + r] + red[128 + r] + red[192 + r];
                l_r[mi][hi] = l_r[mi][hi] * scl[mi][hi] + ladd;
            }

        // rescale O accumulator
        #pragma unroll
        for (int mi = 0; mi < 2; mi++)
            #pragma unroll
            for (int ni = 0; ni < 8; ni++)
                #pragma unroll
                for (int hi = 0; hi < 2; hi++) {
                    oacc[mi][ni][2 * hi    ] *= scl[mi][hi];
                    oacc[mi][ni][2 * hi + 1] *= scl[mi][hi];
                }

        // write P (tf32) to smem
        #pragma unroll
        for (int mi = 0; mi < 2; mi++)
            #pragma unroll
            for (int hi = 0; hi < 2; hi++) {
                int r = lr[mi][hi];
                #pragma unroll
                for (int ni = 0; ni < 4; ni++) {
                    float2 pp = make_float2(rtf(sacc[mi][ni][2 * hi]), rtf(sacc[mi][ni][2 * hi + 1]));
                    *(float2*)&Ps[r * PS_STRIDE + wn * 32 + ni * 8 + 2 * q] = pp;
                }
            }
        __syncthreads();   // P visible across warps

        // ------------------ PV phase: O += P . V over 128 ------------------
        for (int c = 0; c < 8; c++) {
            __syncthreads();
            if (c < 7)          stageV((c + 1) & 1, kb, c + 1);
            else if (kb < 7)    stageK(0, kb + 1, 0);    // prefetch next K block
            if (c < 7 || kb < 7) { CP_COMMIT(); CP_WAIT1(); }
            else                 { CP_WAIT0(); }
            __syncthreads();

            const int buf = c & 1;
            #pragma unroll
            for (int ks = 0; ks < 2; ks++) {
                const int kp = c * 16 + ks * 8;
                unsigned a[2][4], bf[8][2];
                #pragma unroll
                for (int mi = 0; mi < 2; mi++) {
                    int m = wm * 32 + mi * 16;
                    a[mi][0] = __float_as_uint(Ps[(m + g    ) * PS_STRIDE + kp + q    ]);
                    a[mi][1] = __float_as_uint(Ps[(m + g + 8) * PS_STRIDE + kp + q    ]);
                    a[mi][2] = __float_as_uint(Ps[(m + g    ) * PS_STRIDE + kp + q + 4]);
                    a[mi][3] = __float_as_uint(Ps[(m + g + 8) * PS_STRIDE + kp + q + 4]);
                }
                #pragma unroll
                for (int ni = 0; ni < 8; ni++) {
                    int n = wn * 64 + ni * 8;
                    bf[ni][0] = __float_as_uint(Vs[buf * (16 * VS_STRIDE) + (ks * 8 + q    ) * VS_STRIDE + n + g]);
                    bf[ni][1] = __float_as_uint(Vs[buf * (16 * VS_STRIDE) + (ks * 8 + q + 4) * VS_STRIDE + n + g]);
                }
                #pragma unroll
                for (int mi = 0; mi < 2; mi++)
                    #pragma unroll
                    for (int ni = 0; ni < 8; ni++)
                        mma_tf32(oacc[mi][ni], a[mi], bf[ni]);
            }
        }
    }

    // ------------------ epilogue: normalize, zero dead rows, store ------------------
    #pragma unroll
    for (int mi = 0; mi < 2; mi++)
        #pragma unroll
        for (int hi = 0; hi < 2; hi++) {
            bool dead = !(m_r[mi][hi] > -1e37f);
            float inv = dead ? 0.0f : 1.0f / l_r[mi][hi];
            size_t row = (size_t)(b * T_ + m0 + lr[mi][hi]);
            #pragma unroll
            for (int ni = 0; ni < 8; ni++) {
                float2 o = make_float2(rtf(oacc[mi][ni][2 * hi] * inv),
                                       rtf(oacc[mi][ni][2 * hi + 1] * inv));
                *(float2*)&g_o[row * HE_ + h * E_ + wn * 64 + ni * 8 + 2 * q] = o;
            }
        }
}

// ===========================================================================
// Stage 3: out = O [B*T, HE] @ Wfc [HE, E] + bfc
// ===========================================================================
__global__ __launch_bounds__(256) void fc_kernel(const float* __restrict__ bfc,
                                                 float* __restrict__ out)
{
    const int m0 = blockIdx.y * BM;
    const int n0 = blockIdx.x * BN;

    float acc[4][4][4] = {};
    gemm_tc<false>(g_o + (size_t)m0 * HE_, HE_, g_wr + 3 * W_N + n0, E_, HE_, acc);

    Frag f;
    #pragma unroll
    for (int mi = 0; mi < 4; mi++)
        #pragma unroll
        for (int ni = 0; ni < 4; ni++) {
            int c = n0 + f.col(ni);
            float b0 = bfc[c], b1 = bfc[c + 1];
            *(float2*)&out[(size_t)(m0 + f.row(mi, 0)) * E_ + c] =
                make_float2(acc[mi][ni][0] + b0, acc[mi][ni][1] + b1);
            *(float2*)&out[(size_t)(m0 + f.row(mi, 1)) * E_ + c] =
                make_float2(acc[mi][ni][2] + b0, acc[mi][ni][3] + b1);
        }
}

// ===========================================================================
extern "C" void kernel_launch(void* const* d_in, const int* in_sizes, int n_in,
                              void* d_out, int out_size)
{
    const float* x   = (const float*)d_in[0];
    const float* Wq  = (const float*)d_in[1];
    const float* Wk  = (const float*)d_in[2];
    const float* Wv  = (const float*)d_in[3];
    const float* Wfc = (const float*)d_in[4];
    const float* bfc = (const float*)d_in[5];
    const int*   mask = (const int*)d_in[6];

    cudaFuncSetAttribute(flash_kernel, cudaFuncAttributeMaxDynamicSharedMemorySize,
                         FLASH_SMEM_BYTES);

    dim3 blk(256);

    size_t total4 = (XR_N + 4 * W_N) / 4;
    round_kernel<<<(unsigned)(total4 / 256), blk>>>(x, Wq, Wk, Wv, Wfc);

    qkv_kernel<<<dim3(HE_ / BN, (B_ * T_) / BM, 3), blk>>>();

    flash_kernel<<<dim3(T_ / 64, B_ * H_), blk, FLASH_SMEM_BYTES>>>(mask);

    fc_kernel<<<dim3(E_ / BN, (B_ * T_) / BM, 1), blk>>>(bfc, (float*)d_out);
}

// round 6
// speedup vs baseline: 1.1977x; 1.1977x over previous
#include <cuda_runtime.h>

// Problem constants
#define B_   8
#define T_   1024
#define E_   256
#define H_   8
#define HE_  2048   // H_*E_

// GEMM tile config: 128x128 CTA tile, BK=16, 256 threads (8 warps, 2x4), 64x32 warp tile
#define BM   128
#define BN   128
#define BK   16
#define BKP  20     // [m][k] smem row stride (words): 20g+q covers all banks
#define BNP  136    // [k][n] smem row stride (words): 8q+g covers all banks

#define NSTAGE 4
#define STG_WORDS 2560                 // per-operand stage: BM*BKP = 2560 >= 16*136
#define GEMM_SMEM_BYTES (NSTAGE * 2 * STG_WORDS * 4)   // 81920

#define NEG_INF __int_as_float(0xff800000)

// Scratch (static device arrays: allocation-guard-safe)
__device__ float g_qkv[3ULL * B_ * T_ * HE_];   // Q, K, V each [B, T, HE] (tf32-rounded)
__device__ float g_s[(size_t)B_ * H_ * T_ * T_];// scores -> probs [B*H, T, T]
__device__ float g_o[(size_t)B_ * T_ * HE_];    // attn@V [B, T, HE] (tf32-rounded)
__device__ float g_xr[(size_t)B_ * T_ * E_];    // tf32-rounded x
__device__ float g_wr[4ULL * E_ * HE_];         // tf32-rounded Wq, Wk, Wv, Wfc

__device__ __forceinline__ unsigned f2tf32(float f) {
    unsigned u;
    asm("cvt.rna.tf32.f32 %0, %1;" : "=r"(u) : "f"(f));
    return u;
}
__device__ __forceinline__ float rtf(float f) { return __uint_as_float(f2tf32(f)); }

__device__ __forceinline__ void mma_tf32(float c[4], const unsigned a[4], const unsigned b[2]) {
    asm("mma.sync.aligned.m16n8k8.row.col.f32.tf32.tf32.f32 "
        "{%0,%1,%2,%3}, {%4,%5,%6,%7}, {%8,%9}, {%0,%1,%2,%3};"
        : "+f"(c[0]), "+f"(c[1]), "+f"(c[2]), "+f"(c[3])
        : "r"(a[0]), "r"(a[1]), "r"(a[2]), "r"(a[3]), "r"(b[0]), "r"(b[1]));
}

__device__ __forceinline__ void cp16(void* smem_dst, const void* gmem_src) {
    unsigned d = (unsigned)__cvta_generic_to_shared(smem_dst);
    asm volatile("cp.async.cg.shared.global [%0], [%1], 16;" :: "r"(d), "l"(gmem_src));
}
#define CP_COMMIT()  asm volatile("cp.async.commit_group;")

// ===========================================================================
// Tensor-core GEMM mainloop: 4-stage cp.async pipeline, ONE barrier per iter.
// BT=false: B is [K, N] row-major  -> Bs stored [k][BNP]
// BT=true : B is [N, K] row-major  -> C = A * B^T, Bs stored [n][BKP]
// A always [M, K] row-major -> As stored [m][BKP].
// Requires K/BK >= NSTAGE-1 (true everywhere here: K >= 256).
// smem: dynamic, NSTAGE * 2 * STG_WORDS floats.
// ===========================================================================
template <bool BT>
__device__ __forceinline__ void gemm_tc(float* sm,
                                        const float* __restrict__ A, int lda,
                                        const float* __restrict__ Bm, int ldb,
                                        int K, float acc[4][4][4])
{
    const int tid  = threadIdx.x;
    const int lane = tid & 31;
    const int warp = tid >> 5;
    const int wm   = warp >> 2;
    const int wn   = warp & 3;
    const int g    = lane >> 2;
    const int q    = lane & 3;

    auto stage = [&](int s, int k0) {
        float* As = sm + (2 * s    ) * STG_WORDS;
        float* Bs = sm + (2 * s + 1) * STG_WORDS;
        #pragma unroll
        for (int i = 0; i < 2; i++) {
            int c  = tid + i * 256;
            int m  = c >> 2;
            int ko = (c & 3) * 4;
            cp16(&As[m * BKP + ko], A + (size_t)m * lda + k0 + ko);
        }
        #pragma unroll
        for (int i = 0; i < 2; i++) {
            int c = tid + i * 256;
            if (BT) {
                int n  = c >> 2;
                int ko = (c & 3) * 4;
                cp16(&Bs[n * BKP + ko], Bm + (size_t)n * ldb + k0 + ko);
            } else {
                int kk = c >> 5;
                int no = (c & 31) * 4;
                cp16(&Bs[kk * BNP + no], Bm + (size_t)(k0 + kk) * ldb + no);
            }
        }
        CP_COMMIT();
    };

    const int niter = K / BK;

    // prologue: fill NSTAGE-1 stages
    #pragma unroll
    for (int s = 0; s < NSTAGE - 1; s++)
        stage(s, s * BK);

    for (int it = 0; it < niter; it++) {
        // wait until group `it` has landed (exact count at the tail)
        int rem = niter - 1 - it;
        if (rem >= 2)      asm volatile("cp.async.wait_group 2;");
        else if (rem == 1) asm volatile("cp.async.wait_group 1;");
        else               asm volatile("cp.async.wait_group 0;");
        __syncthreads();   // also guards reuse of buffer (it+NSTAGE-1)%NSTAGE

        if (it + NSTAGE - 1 < niter)
            stage((it + NSTAGE - 1) % NSTAGE, (it + NSTAGE - 1) * BK);

        const int buf = it % NSTAGE;
        const float* As = sm + (2 * buf    ) * STG_WORDS;
        const float* Bs = sm + (2 * buf + 1) * STG_WORDS;

        #pragma unroll
        for (int ks = 0; ks < 2; ks++) {
            const int kb = ks * 8;
            unsigned a[4][4], b[4][2];
            #pragma unroll
            for (int mi = 0; mi < 4; mi++) {
                int m = wm * 64 + mi * 16;
                a[mi][0] = __float_as_uint(As[(m + g    ) * BKP + kb + q    ]);
                a[mi][1] = __float_as_uint(As[(m + g + 8) * BKP + kb + q    ]);
                a[mi][2] = __float_as_uint(As[(m + g    ) * BKP + kb + q + 4]);
                a[mi][3] = __float_as_uint(As[(m + g + 8) * BKP + kb + q + 4]);
            }
            #pragma unroll
            for (int ni = 0; ni < 4; ni++) {
                int n = wn * 32 + ni * 8;
                if (BT) {
                    b[ni][0] = __float_as_uint(Bs[(n + g) * BKP + kb + q    ]);
                    b[ni][1] = __float_as_uint(Bs[(n + g) * BKP + kb + q + 4]);
                } else {
                    b[ni][0] = __float_as_uint(Bs[(kb + q    ) * BNP + n + g]);
                    b[ni][1] = __float_as_uint(Bs[(kb + q + 4) * BNP + n + g]);
                }
            }
            #pragma unroll
            for (int mi = 0; mi < 4; mi++)
                #pragma unroll
                for (int ni = 0; ni < 4; ni++)
                    mma_tf32(acc[mi][ni], a[mi], b[ni]);
        }
    }
    __syncthreads();
}

struct Frag {
    int wm, wn, g, q;
    __device__ __forceinline__ Frag() {
        int tid = threadIdx.x, lane = tid & 31, warp = tid >> 5;
        wm = warp >> 2; wn = warp & 3; g = lane >> 2; q = lane & 3;
    }
    __device__ __forceinline__ int row(int mi, int hi) const { return wm * 64 + mi * 16 + g + hi * 8; }
    __device__ __forceinline__ int col(int ni) const { return wn * 32 + ni * 8 + 2 * q; }
};

// ===========================================================================
// Stage 0: pre-round inputs to tf32
// ===========================================================================
#define XR_N   ((size_t)B_ * T_ * E_)
#define W_N    ((size_t)E_ * HE_)
__global__ __launch_bounds__(256) void round_kernel(const float* __restrict__ x,
                                                    const float* __restrict__ Wq,
                                                    const float* __restrict__ Wk,
                                                    const float* __restrict__ Wv,
                                                    const float* __restrict__ Wfc)
{
    size_t i = ((size_t)blockIdx.x * 256 + threadIdx.x) * 4;
    const float* src;
    float* dst;
    size_t off;
    if (i < XR_N)                 { src = x;   dst = g_xr;            off = i; }
    else if (i < XR_N + W_N)      { src = Wq;  dst = g_wr;            off = i - XR_N; }
    else if (i < XR_N + 2 * W_N)  { src = Wk;  dst = g_wr + W_N;      off = i - XR_N - W_N; }
    else if (i < XR_N + 3 * W_N)  { src = Wv;  dst = g_wr + 2 * W_N;  off = i - XR_N - 2 * W_N; }
    else                          { src = Wfc; dst = g_wr + 3 * W_N;  off = i - XR_N - 3 * W_N; }
    float4 v = *(const float4*)(src + off);
    v.x = rtf(v.x); v.y = rtf(v.y); v.z = rtf(v.z); v.w = rtf(v.w);
    *(float4*)(dst + off) = v;
}

// ===========================================================================
// Stage 1: QKV projections. z=0:Q (scaled 1/16), z=1:K, z=2:V. tf32-rounded out.
// ===========================================================================
__global__ __launch_bounds__(256) void qkv_kernel()
{
    extern __shared__ float sm[];
    const int z = blockIdx.z;
    const float* W = g_wr + (size_t)z * W_N;
    const float scale = (z == 0) ? 0.0625f : 1.0f;
    float* C = g_qkv + (size_t)z * B_ * T_ * HE_;

    const int m0 = blockIdx.y * BM;
    const int n0 = blockIdx.x * BN;

    float acc[4][4][4] = {};
    gemm_tc<false>(sm, g_xr + (size_t)m0 * E_, E_, W + n0, HE_, E_, acc);

    Frag f;
    #pragma unroll
    for (int mi = 0; mi < 4; mi++)
        #pragma unroll
        for (int ni = 0; ni < 4; ni++) {
            int c = n0 + f.col(ni);
            *(float2*)&C[(size_t)(m0 + f.row(mi, 0)) * HE_ + c] =
                make_float2(rtf(acc[mi][ni][0] * scale), rtf(acc[mi][ni][1] * scale));
            *(float2*)&C[(size_t)(m0 + f.row(mi, 1)) * HE_ + c] =
                make_float2(rtf(acc[mi][ni][2] * scale), rtf(acc[mi][ni][3] * scale));
        }
}

// ===========================================================================
// Stage 2: scores S = Q.K^T with mask -> -inf. mask int32 [B,T,T]
// ===========================================================================
__global__ __launch_bounds__(256) void scores_kernel(const int* __restrict__ mask)
{
    extern __shared__ float sm[];
    const int z = blockIdx.z;   // b*H + h
    const int b = z >> 3;
    const int h = z & 7;

    const float* Q = g_qkv + (size_t)b * T_ * HE_ + h * E_;
    const float* K = g_qkv + (size_t)B_ * T_ * HE_ + (size_t)b * T_ * HE_ + h * E_;

    const int m0 = blockIdx.y * BM;
    const int n0 = blockIdx.x * BN;

    float acc[4][4][4] = {};
    gemm_tc<true>(sm, Q + (size_t)m0 * HE_, HE_, K + (size_t)n0 * HE_, HE_, E_, acc);

    float* S = g_s + (size_t)z * T_ * T_;
    const int* mrow = mask + (size_t)b * T_ * T_;

    Frag f;
    #pragma unroll
    for (int mi = 0; mi < 4; mi++)
        #pragma unroll
        for (int ni = 0; ni < 4; ni++) {
            int c = n0 + f.col(ni);
            #pragma unroll
            for (int hi = 0; hi < 2; hi++) {
                size_t r = (size_t)(m0 + f.row(mi, hi)) * T_;
                int2 mk = *(const int2*)&mrow[r + c];
                float v0 = mk.x ? NEG_INF : acc[mi][ni][hi * 2    ];
                float v1 = mk.y ? NEG_INF : acc[mi][ni][hi * 2 + 1];
                *(float2*)&S[r + c] = make_float2(v0, v1);
            }
        }
}

// ===========================================================================
// Stage 3: row softmax over T=1024; fully-masked rows -> 0. Output tf32-rounded.
// ===========================================================================
__global__ __launch_bounds__(256) void softmax_kernel()
{
    float* p = g_s + (size_t)blockIdx.x * T_;
    const int t = threadIdx.x;

    float4 v = ((const float4*)p)[t];
    float mx = fmaxf(fmaxf(v.x, v.y), fmaxf(v.z, v.w));

    __shared__ float red[8];
    #pragma unroll
    for (int o = 16; o > 0; o >>= 1)
        mx = fmaxf(mx, __shfl_xor_sync(0xffffffff, mx, o));
    if ((t & 31) == 0) red[t >> 5] = mx;
    __syncthreads();
    float bm = red[0];
    #pragma unroll
    for (int i = 1; i < 8; i++) bm = fmaxf(bm, red[i]);
    __syncthreads();

    float4 e;
    float s;
    if (bm == NEG_INF) {
        e.x = e.y = e.z = e.w = 0.0f;
        s = 0.0f;
    } else {
        e.x = __expf(v.x - bm);
        e.y = __expf(v.y - bm);
        e.z = __expf(v.z - bm);
        e.w = __expf(v.w - bm);
        s = e.x + e.y + e.z + e.w;
    }
    #pragma unroll
    for (int o = 16; o > 0; o >>= 1)
        s += __shfl_xor_sync(0xffffffff, s, o);
    if ((t & 31) == 0) red[t >> 5] = s;
    __syncthreads();
    float tot = red[0];
    #pragma unroll
    for (int i = 1; i < 8; i++) tot += red[i];

    float inv = (tot > 0.0f) ? (1.0f / tot) : 0.0f;
    e.x = rtf(e.x * inv); e.y = rtf(e.y * inv);
    e.z = rtf(e.z * inv); e.w = rtf(e.w * inv);
    ((float4*)p)[t] = e;
}

// ===========================================================================
// Stage 4: O[b,q,h,:] = sum_k P[b,h,q,k] * V[b,k,h,:]. Output tf32-rounded.
// ===========================================================================
__global__ __launch_bounds__(256) void attnv_kernel()
{
    extern __shared__ float sm[];
    const int z = blockIdx.z;
    const int b = z >> 3;
    const int h = z & 7;

    const float* S = g_s + (size_t)z * T_ * T_;
    const float* V = g_qkv + 2ULL * B_ * T_ * HE_ + (size_t)b * T_ * HE_ + h * E_;

    const int m0 = blockIdx.y * BM;
    const int n0 = blockIdx.x * BN;

    float acc[4][4][4] = {};
    gemm_tc<false>(sm, S + (size_t)m0 * T_, T_, V + n0, HE_, T_, acc);

    float* O = g_o + (size_t)b * T_ * HE_ + h * E_;
    Frag f;
    #pragma unroll
    for (int mi = 0; mi < 4; mi++)
        #pragma unroll
        for (int ni = 0; ni < 4; ni++) {
            int c = n0 + f.col(ni);
            *(float2*)&O[(size_t)(m0 + f.row(mi, 0)) * HE_ + c] =
                make_float2(rtf(acc[mi][ni][0]), rtf(acc[mi][ni][1]));
            *(float2*)&O[(size_t)(m0 + f.row(mi, 1)) * HE_ + c] =
                make_float2(rtf(acc[mi][ni][2]), rtf(acc[mi][ni][3]));
        }
}

// ===========================================================================
// Stage 5: out = O [B*T, HE] @ Wfc [HE, E] + bfc
// ===========================================================================
__global__ __launch_bounds__(256) void fc_kernel(const float* __restrict__ bfc,
                                                 float* __restrict__ out)
{
    extern __shared__ float sm[];
    const int m0 = blockIdx.y * BM;
    const int n0 = blockIdx.x * BN;

    float acc[4][4][4] = {};
    gemm_tc<false>(sm, g_o + (size_t)m0 * HE_, HE_, g_wr + 3 * W_N + n0, E_, HE_, acc);

    Frag f;
    #pragma unroll
    for (int mi = 0; mi < 4; mi++)
        #pragma unroll
        for (int ni = 0; ni < 4; ni++) {
            int c = n0 + f.col(ni);
            float b0 = bfc[c], b1 = bfc[c + 1];
            *(float2*)&out[(size_t)(m0 + f.row(mi, 0)) * E_ + c] =
                make_float2(acc[mi][ni][0] + b0, acc[mi][ni][1] + b1);
            *(float2*)&out[(size_t)(m0 + f.row(mi, 1)) * E_ + c] =
                make_float2(acc[mi][ni][2] + b0, acc[mi][ni][3] + b1);
        }
}

// ===========================================================================
extern "C" void kernel_launch(void* const* d_in, const int* in_sizes, int n_in,
                              void* d_out, int out_size)
{
    const float* x   = (const float*)d_in[0];
    const float* Wq  = (const float*)d_in[1];
    const float* Wk  = (const float*)d_in[2];
    const float* Wv  = (const float*)d_in[3];
    const float* Wfc = (const float*)d_in[4];
    const float* bfc = (const float*)d_in[5];
    const int*   mask = (const int*)d_in[6];

    static int attr_done = 0;
    if (!attr_done) {
        cudaFuncSetAttribute(qkv_kernel,    cudaFuncAttributeMaxDynamicSharedMemorySize, GEMM_SMEM_BYTES);
        cudaFuncSetAttribute(scores_kernel, cudaFuncAttributeMaxDynamicSharedMemorySize, GEMM_SMEM_BYTES);
        cudaFuncSetAttribute(attnv_kernel,  cudaFuncAttributeMaxDynamicSharedMemorySize, GEMM_SMEM_BYTES);
        cudaFuncSetAttribute(fc_kernel,     cudaFuncAttributeMaxDynamicSharedMemorySize, GEMM_SMEM_BYTES);
        attr_done = 1;
    }

    dim3 blk(256);

    size_t total4 = (XR_N + 4 * W_N) / 4;
    round_kernel<<<(unsigned)(total4 / 256), blk>>>(x, Wq, Wk, Wv, Wfc);

    qkv_kernel<<<dim3(HE_ / BN, (B_ * T_) / BM, 3), blk, GEMM_SMEM_BYTES>>>();
    scores_kernel<<<dim3(T_ / BN, T_ / BM, B_ * H_), blk, GEMM_SMEM_BYTES>>>(mask);
    softmax_kernel<<<B_ * H_ * T_, 256>>>();
    attnv_kernel<<<dim3(E_ / BN, T_ / BM, B_ * H_), blk, GEMM_SMEM_BYTES>>>();
    fc_kernel<<<dim3(E_ / BN, (B_ * T_) / BM, 1), blk, GEMM_SMEM_BYTES>>>(bfc, (float*)d_out);
}

// round 7
// speedup vs baseline: 1.3525x; 1.1293x over previous
#include <cuda_runtime.h>

// Problem constants
#define B_   8
#define T_   1024
#define E_   256
#define H_   8
#define HE_  2048   // H_*E_

// GEMM tile config: 128x128 CTA tile, BK=32, 256 threads (8 warps, 2x4), 64x32 warp tile
#define BM   128
#define BN   128
#define BK   32
#define BKP  36     // [m][k] smem row stride (words): bank = 4g+q+const -> conflict-free
#define BNP  136    // [k][n] smem row stride (words): bank = 8q+g+const -> conflict-free

#define NSTAGE 3
#define STG_WORDS (BM * BKP)                           // 4608 (>= 32*136=4352)
#define GEMM_SMEM_BYTES (NSTAGE * 2 * STG_WORDS * 4)   // 110592 -> 2 CTAs/SM

#define NEG_INF __int_as_float(0xff800000)

// Scratch (static device arrays: allocation-guard-safe)
__device__ float g_qkv[3ULL * B_ * T_ * HE_];   // Q, K, V each [B, T, HE] (tf32-rounded)
__device__ float g_s[(size_t)B_ * H_ * T_ * T_];// scores -> probs [B*H, T, T]
__device__ float g_o[(size_t)B_ * T_ * HE_];    // attn@V [B, T, HE] (tf32-rounded)
__device__ float g_xr[(size_t)B_ * T_ * E_];    // tf32-rounded x
__device__ float g_wr[4ULL * E_ * HE_];         // tf32-rounded Wq, Wk, Wv, Wfc

__device__ __forceinline__ unsigned f2tf32(float f) {
    unsigned u;
    asm("cvt.rna.tf32.f32 %0, %1;" : "=r"(u) : "f"(f));
    return u;
}
__device__ __forceinline__ float rtf(float f) { return __uint_as_float(f2tf32(f)); }

__device__ __forceinline__ void mma_tf32(float c[4], const unsigned a[4], const unsigned b[2]) {
    asm("mma.sync.aligned.m16n8k8.row.col.f32.tf32.tf32.f32 "
        "{%0,%1,%2,%3}, {%4,%5,%6,%7}, {%8,%9}, {%0,%1,%2,%3};"
        : "+f"(c[0]), "+f"(c[1]), "+f"(c[2]), "+f"(c[3])
        : "r"(a[0]), "r"(a[1]), "r"(a[2]), "r"(a[3]), "r"(b[0]), "r"(b[1]));
}

__device__ __forceinline__ void cp16(void* smem_dst, const void* gmem_src) {
    unsigned d = (unsigned)__cvta_generic_to_shared(smem_dst);
    asm volatile("cp.async.cg.shared.global [%0], [%1], 16;" :: "r"(d), "l"(gmem_src));
}
#define CP_COMMIT()  asm volatile("cp.async.commit_group;")

// ===========================================================================
// Tensor-core GEMM mainloop: 3-stage cp.async pipeline, BK=32,
// ONE barrier per iteration (64 MMAs/warp between barriers).
// BT=false: B is [K, N] row-major  -> Bs stored [k][BNP]
// BT=true : B is [N, K] row-major  -> C = A * B^T, Bs stored [n][BKP]
// A always [M, K] row-major -> As stored [m][BKP].
// Requires K/BK >= NSTAGE-1 = 2 (min K here is 256 -> 8 iters).
// ===========================================================================
template <bool BT>
__device__ __forceinline__ void gemm_tc(float* sm,
                                        const float* __restrict__ A, int lda,
                                        const float* __restrict__ Bm, int ldb,
                                        int K, float acc[4][4][4])
{
    const int tid  = threadIdx.x;
    const int lane = tid & 31;
    const int warp = tid >> 5;
    const int wm   = warp >> 2;
    const int wn   = warp & 3;
    const int g    = lane >> 2;
    const int q    = lane & 3;

    auto stage = [&](int s, int k0) {
        float* As = sm + (2 * s    ) * STG_WORDS;
        float* Bs = sm + (2 * s + 1) * STG_WORDS;
        #pragma unroll
        for (int i = 0; i < 4; i++) {           // A: 128x32 = 1024 float4, 4/thread
            int c  = tid + i * 256;
            int m  = c >> 3;
            int ko = (c & 7) * 4;
            cp16(&As[m * BKP + ko], A + (size_t)m * lda + k0 + ko);
        }
        #pragma unroll
        for (int i = 0; i < 4; i++) {
            int c = tid + i * 256;
            if (BT) {
                int n  = c >> 3;
                int ko = (c & 7) * 4;
                cp16(&Bs[n * BKP + ko], Bm + (size_t)n * ldb + k0 + ko);
            } else {
                int kk = c >> 5;
                int no = (c & 31) * 4;
                cp16(&Bs[kk * BNP + no], Bm + (size_t)(k0 + kk) * ldb + no);
            }
        }
        CP_COMMIT();
    };

    const int niter = K / BK;

    // prologue: fill NSTAGE-1 stages
    #pragma unroll
    for (int s = 0; s < NSTAGE - 1; s++)
        stage(s, s * BK);

    for (int it = 0; it < niter; it++) {
        // group `it` must be complete before consuming buffer it%NSTAGE
        if (it < niter - 1) asm volatile("cp.async.wait_group 1;");
        else                asm volatile("cp.async.wait_group 0;");
        __syncthreads();    // also guards reuse of buffer (it+2)%3 (consumed at it-1)

        if (it + NSTAGE - 1 < niter)
            stage((it + NSTAGE - 1) % NSTAGE, (it + NSTAGE - 1) * BK);

        const int buf = it % NSTAGE;
        const float* As = sm + (2 * buf    ) * STG_WORDS;
        const float* Bs = sm + (2 * buf + 1) * STG_WORDS;

        #pragma unroll
        for (int ks = 0; ks < 4; ks++) {
            const int kb = ks * 8;
            unsigned a[4][4], b[4][2];
            #pragma unroll
            for (int mi = 0; mi < 4; mi++) {
                int m = wm * 64 + mi * 16;
                a[mi][0] = __float_as_uint(As[(m + g    ) * BKP + kb + q    ]);
                a[mi][1] = __float_as_uint(As[(m + g + 8) * BKP + kb + q    ]);
                a[mi][2] = __float_as_uint(As[(m + g    ) * BKP + kb + q + 4]);
                a[mi][3] = __float_as_uint(As[(m + g + 8) * BKP + kb + q + 4]);
            }
            #pragma unroll
            for (int ni = 0; ni < 4; ni++) {
                int n = wn * 32 + ni * 8;
                if (BT) {
                    b[ni][0] = __float_as_uint(Bs[(n + g) * BKP + kb + q    ]);
                    b[ni][1] = __float_as_uint(Bs[(n + g) * BKP + kb + q + 4]);
                } else {
                    b[ni][0] = __float_as_uint(Bs[(kb + q    ) * BNP + n + g]);
                    b[ni][1] = __float_as_uint(Bs[(kb + q + 4) * BNP + n + g]);
                }
            }
            #pragma unroll
            for (int mi = 0; mi < 4; mi++)
                #pragma unroll
                for (int ni = 0; ni < 4; ni++)
                    mma_tf32(acc[mi][ni], a[mi], b[ni]);
        }
    }
    __syncthreads();
}

struct Frag {
    int wm, wn, g, q;
    __device__ __forceinline__ Frag() {
        int tid = threadIdx.x, lane = tid & 31, warp = tid >> 5;
        wm = warp >> 2; wn = warp & 3; g = lane >> 2; q = lane & 3;
    }
    __device__ __forceinline__ int row(int mi, int hi) const { return wm * 64 + mi * 16 + g + hi * 8; }
    __device__ __forceinline__ int col(int ni) const { return wn * 32 + ni * 8 + 2 * q; }
};

// ===========================================================================
// Stage 0: pre-round inputs to tf32
// ===========================================================================
#define XR_N   ((size_t)B_ * T_ * E_)
#define W_N    ((size_t)E_ * HE_)
__global__ __launch_bounds__(256) void round_kernel(const float* __restrict__ x,
                                                    const float* __restrict__ Wq,
                                                    const float* __restrict__ Wk,
                                                    const float* __restrict__ Wv,
                                                    const float* __restrict__ Wfc)
{
    size_t i = ((size_t)blockIdx.x * 256 + threadIdx.x) * 4;
    const float* src;
    float* dst;
    size_t off;
    if (i < XR_N)                 { src = x;   dst = g_xr;            off = i; }
    else if (i < XR_N + W_N)      { src = Wq;  dst = g_wr;            off = i - XR_N; }
    else if (i < XR_N + 2 * W_N)  { src = Wk;  dst = g_wr + W_N;      off = i - XR_N - W_N; }
    else if (i < XR_N + 3 * W_N)  { src = Wv;  dst = g_wr + 2 * W_N;  off = i - XR_N - 2 * W_N; }
    else                          { src = Wfc; dst = g_wr + 3 * W_N;  off = i - XR_N - 3 * W_N; }
    float4 v = *(const float4*)(src + off);
    v.x = rtf(v.x); v.y = rtf(v.y); v.z = rtf(v.z); v.w = rtf(v.w);
    *(float4*)(dst + off) = v;
}

// ===========================================================================
// Stage 1: QKV projections. z=0:Q (scaled 1/16), z=1:K, z=2:V. tf32-rounded out.
// ===========================================================================
__global__ __launch_bounds__(256, 2) void qkv_kernel()
{
    extern __shared__ float sm[];
    const int z = blockIdx.z;
    const float* W = g_wr + (size_t)z * W_N;
    const float scale = (z == 0) ? 0.0625f : 1.0f;
    float* C = g_qkv + (size_t)z * B_ * T_ * HE_;

    const int m0 = blockIdx.y * BM;
    const int n0 = blockIdx.x * BN;

    float acc[4][4][4] = {};
    gemm_tc<false>(sm, g_xr + (size_t)m0 * E_, E_, W + n0, HE_, E_, acc);

    Frag f;
    #pragma unroll
    for (int mi = 0; mi < 4; mi++)
        #pragma unroll
        for (int ni = 0; ni < 4; ni++) {
            int c = n0 + f.col(ni);
            *(float2*)&C[(size_t)(m0 + f.row(mi, 0)) * HE_ + c] =
                make_float2(rtf(acc[mi][ni][0] * scale), rtf(acc[mi][ni][1] * scale));
            *(float2*)&C[(size_t)(m0 + f.row(mi, 1)) * HE_ + c] =
                make_float2(rtf(acc[mi][ni][2] * scale), rtf(acc[mi][ni][3] * scale));
        }
}

// ===========================================================================
// Stage 2: scores S = Q.K^T with mask -> -inf. mask int32 [B,T,T]
// ===========================================================================
__global__ __launch_bounds__(256, 2) void scores_kernel(const int* __restrict__ mask)
{
    extern __shared__ float sm[];
    const int z = blockIdx.z;   // b*H + h
    const int b = z >> 3;
    const int h = z & 7;

    const float* Q = g_qkv + (size_t)b * T_ * HE_ + h * E_;
    const float* K = g_qkv + (size_t)B_ * T_ * HE_ + (size_t)b * T_ * HE_ + h * E_;

    const int m0 = blockIdx.y * BM;
    const int n0 = blockIdx.x * BN;

    float acc[4][4][4] = {};
    gemm_tc<true>(sm, Q + (size_t)m0 * HE_, HE_, K + (size_t)n0 * HE_, HE_, E_, acc);

    float* S = g_s + (size_t)z * T_ * T_;
    const int* mrow = mask + (size_t)b * T_ * T_;

    Frag f;
    #pragma unroll
    for (int mi = 0; mi < 4; mi++)
        #pragma unroll
        for (int ni = 0; ni < 4; ni++) {
            int c = n0 + f.col(ni);
            #pragma unroll
            for (int hi = 0; hi < 2; hi++) {
                size_t r = (size_t)(m0 + f.row(mi, hi)) * T_;
                int2 mk = *(const int2*)&mrow[r + c];
                float v0 = mk.x ? NEG_INF : acc[mi][ni][hi * 2    ];
                float v1 = mk.y ? NEG_INF : acc[mi][ni][hi * 2 + 1];
                *(float2*)&S[r + c] = make_float2(v0, v1);
            }
        }
}

// ===========================================================================
// Stage 3: row softmax over T=1024; fully-masked rows -> 0. Output tf32-rounded.
// ===========================================================================
__global__ __launch_bounds__(256) void softmax_kernel()
{
    float* p = g_s + (size_t)blockIdx.x * T_;
    const int t = threadIdx.x;

    float4 v = ((const float4*)p)[t];
    float mx = fmaxf(fmaxf(v.x, v.y), fmaxf(v.z, v.w));

    __shared__ float red[8];
    #pragma unroll
    for (int o = 16; o > 0; o >>= 1)
        mx = fmaxf(mx, __shfl_xor_sync(0xffffffff, mx, o));
    if ((t & 31) == 0) red[t >> 5] = mx;
    __syncthreads();
    float bm = red[0];
    #pragma unroll
    for (int i = 1; i < 8; i++) bm = fmaxf(bm, red[i]);
    __syncthreads();

    float4 e;
    float s;
    if (bm == NEG_INF) {
        e.x = e.y = e.z = e.w = 0.0f;
        s = 0.0f;
    } else {
        e.x = __expf(v.x - bm);
        e.y = __expf(v.y - bm);
        e.z = __expf(v.z - bm);
        e.w = __expf(v.w - bm);
        s = e.x + e.y + e.z + e.w;
    }
    #pragma unroll
    for (int o = 16; o > 0; o >>= 1)
        s += __shfl_xor_sync(0xffffffff, s, o);
    if ((t & 31) == 0) red[t >> 5] = s;
    __syncthreads();
    float tot = red[0];
    #pragma unroll
    for (int i = 1; i < 8; i++) tot += red[i];

    float inv = (tot > 0.0f) ? (1.0f / tot) : 0.0f;
    e.x = rtf(e.x * inv); e.y = rtf(e.y * inv);
    e.z = rtf(e.z * inv); e.w = rtf(e.w * inv);
    ((float4*)p)[t] = e;
}

// ===========================================================================
// Stage 4: O[b,q,h,:] = sum_k P[b,h,q,k] * V[b,k,h,:]. Output tf32-rounded.
// ===========================================================================
__global__ __launch_bounds__(256, 2) void attnv_kernel()
{
    extern __shared__ float sm[];
    const int z = blockIdx.z;
    const int b = z >> 3;
    const int h = z & 7;

    const float* S = g_s + (size_t)z * T_ * T_;
    const float* V = g_qkv + 2ULL * B_ * T_ * HE_ + (size_t)b * T_ * HE_ + h * E_;

    const int m0 = blockIdx.y * BM;
    const int n0 = blockIdx.x * BN;

    float acc[4][4][4] = {};
    gemm_tc<false>(sm, S + (size_t)m0 * T_, T_, V + n0, HE_, T_, acc);

    float* O = g_o + (size_t)b * T_ * HE_ + h * E_;
    Frag f;
    #pragma unroll
    for (int mi = 0; mi < 4; mi++)
        #pragma unroll
        for (int ni = 0; ni < 4; ni++) {
            int c = n0 + f.col(ni);
            *(float2*)&O[(size_t)(m0 + f.row(mi, 0)) * HE_ + c] =
                make_float2(rtf(acc[mi][ni][0]), rtf(acc[mi][ni][1]));
            *(float2*)&O[(size_t)(m0 + f.row(mi, 1)) * HE_ + c] =
                make_float2(rtf(acc[mi][ni][2]), rtf(acc[mi][ni][3]));
        }
}

// ===========================================================================
// Stage 5: out = O [B*T, HE] @ Wfc [HE, E] + bfc
// ===========================================================================
__global__ __launch_bounds__(256, 2) void fc_kernel(const float* __restrict__ bfc,
                                                    float* __restrict__ out)
{
    extern __shared__ float sm[];
    const int m0 = blockIdx.y * BM;
    const int n0 = blockIdx.x * BN;

    float acc[4][4][4] = {};
    gemm_tc<false>(sm, g_o + (size_t)m0 * HE_, HE_, g_wr + 3 * W_N + n0, E_, HE_, acc);

    Frag f;
    #pragma unroll
    for (int mi = 0; mi < 4; mi++)
        #pragma unroll
        for (int ni = 0; ni < 4; ni++) {
            int c = n0 + f.col(ni);
            float b0 = bfc[c], b1 = bfc[c + 1];
            *(float2*)&out[(size_t)(m0 + f.row(mi, 0)) * E_ + c] =
                make_float2(acc[mi][ni][0] + b0, acc[mi][ni][1] + b1);
            *(float2*)&out[(size_t)(m0 + f.row(mi, 1)) * E_ + c] =
                make_float2(acc[mi][ni][2] + b0, acc[mi][ni][3] + b1);
        }
}

// ===========================================================================
extern "C" void kernel_launch(void* const* d_in, const int* in_sizes, int n_in,
                              void* d_out, int out_size)
{
    const float* x   = (const float*)d_in[0];
    const float* Wq  = (const float*)d_in[1];
    const float* Wk  = (const float*)d_in[2];
    const float* Wv  = (const float*)d_in[3];
    const float* Wfc = (const float*)d_in[4];
    const float* bfc = (const float*)d_in[5];
    const int*   mask = (const int*)d_in[6];

    static int attr_done = 0;
    if (!attr_done) {
        cudaFuncSetAttribute(qkv_kernel,    cudaFuncAttributeMaxDynamicSharedMemorySize, GEMM_SMEM_BYTES);
        cudaFuncSetAttribute(scores_kernel, cudaFuncAttributeMaxDynamicSharedMemorySize, GEMM_SMEM_BYTES);
        cudaFuncSetAttribute(attnv_kernel,  cudaFuncAttributeMaxDynamicSharedMemorySize, GEMM_SMEM_BYTES);
        cudaFuncSetAttribute(fc_kernel,     cudaFuncAttributeMaxDynamicSharedMemorySize, GEMM_SMEM_BYTES);
        attr_done = 1;
    }

    dim3 blk(256);

    size_t total4 = (XR_N + 4 * W_N) / 4;
    round_kernel<<<(unsigned)(total4 / 256), blk>>>(x, Wq, Wk, Wv, Wfc);

    qkv_kernel<<<dim3(HE_ / BN, (B_ * T_) / BM, 3), blk, GEMM_SMEM_BYTES>>>();
    scores_kernel<<<dim3(T_ / BN, T_ / BM, B_ * H_), blk, GEMM_SMEM_BYTES>>>(mask);
    softmax_kernel<<<B_ * H_ * T_, 256>>>();
    attnv_kernel<<<dim3(E_ / BN, T_ / BM, B_ * H_), blk, GEMM_SMEM_BYTES>>>();
    fc_kernel<<<dim3(E_ / BN, (B_ * T_) / BM, 1), blk, GEMM_SMEM_BYTES>>>(bfc, (float*)d_out);
}